// round 7
// baseline (speedup 1.0000x reference)
#include <cuda_runtime.h>
#include <cuda_bf16.h>
#include <math.h>
#include <cstdint>

#define D      1024
#define D3     3072
#define D4     4096
#define TSEQ   2048
#define NBATCH 2
#define NTOK   4096
#define NH     16
#define HD     64
#define EPS    1.1920929e-07f

// ---------------------------------------------------------------------------
// Scratch (device globals; no allocations allowed)
// ---------------------------------------------------------------------------
__device__ __nv_bfloat16 g_ah[NTOK * D];    // activation hi
__device__ __nv_bfloat16 g_al[NTOK * D];    // activation lo
__device__ __nv_bfloat16 g_bh[NTOK * D4];   // fc1 output hi
__device__ __nv_bfloat16 g_bl[NTOK * D4];   // fc1 output lo
__device__ __nv_bfloat16 g_wth[D * D4];     // transposed weight hi (shared)
__device__ __nv_bfloat16 g_wtl[D * D4];     // transposed weight lo (shared)
// pre-split q/k/v, layout [b, h, t, d] (row = 64 bf16 = 128B)
__device__ __nv_bfloat16 g_qh[NTOK * D];
__device__ __nv_bfloat16 g_ql[NTOK * D];
__device__ __nv_bfloat16 g_kh[NTOK * D];
__device__ __nv_bfloat16 g_kl[NTOK * D];
__device__ __nv_bfloat16 g_vh[NTOK * D];
__device__ __nv_bfloat16 g_vl[NTOK * D];

// ---------------------------------------------------------------------------
// Helpers
// ---------------------------------------------------------------------------
__device__ __forceinline__ uint32_t smem_to_u32(const void* p) {
    uint32_t a;
    asm("{ .reg .u64 t; cvta.to.shared.u64 t, %1; cvt.u32.u64 %0, t; }" : "=r"(a) : "l"(p));
    return a;
}

// chunk-xor swizzle: 16B chunk index ^= (row & 7)
#define SWZ(off) ((uint32_t)(off) ^ ((((uint32_t)(off) >> 7) & 7) << 4))

__device__ __forceinline__ void ldsm_x4(uint32_t* r, uint32_t addr) {
    asm volatile("ldmatrix.sync.aligned.m8n8.x4.shared.b16 {%0,%1,%2,%3}, [%4];"
                 : "=r"(r[0]), "=r"(r[1]), "=r"(r[2]), "=r"(r[3]) : "r"(addr));
}
__device__ __forceinline__ void ldsm_x2(uint32_t* r, uint32_t addr) {
    asm volatile("ldmatrix.sync.aligned.m8n8.x2.shared.b16 {%0,%1}, [%2];"
                 : "=r"(r[0]), "=r"(r[1]) : "r"(addr));
}
__device__ __forceinline__ void ldsm_x2_trans(uint32_t* r, uint32_t addr) {
    asm volatile("ldmatrix.sync.aligned.m8n8.x2.trans.shared.b16 {%0,%1}, [%2];"
                 : "=r"(r[0]), "=r"(r[1]) : "r"(addr));
}
__device__ __forceinline__ void mma_bf16_g(float* d, const uint32_t* a, const uint32_t* b) {
    asm volatile(
        "mma.sync.aligned.m16n8k16.row.col.f32.bf16.bf16.f32 "
        "{%0,%1,%2,%3}, {%4,%5,%6,%7}, {%8,%9}, {%0,%1,%2,%3};"
        : "+f"(d[0]), "+f"(d[1]), "+f"(d[2]), "+f"(d[3])
        : "r"(a[0]), "r"(a[1]), "r"(a[2]), "r"(a[3]), "r"(b[0]), "r"(b[1]));
}

__device__ __forceinline__ void split2(float v, __nv_bfloat16& h, __nv_bfloat16& l) {
    h = __float2bfloat16(v);
    l = __float2bfloat16(v - __bfloat162float(h));
}
__device__ __forceinline__ uint32_t pack_bf16x2(float a, float b) {
    uint32_t r;
    asm("cvt.rn.bf16x2.f32 %0, %1, %2;" : "=r"(r) : "f"(b), "f"(a));
    return r;
}
__device__ __forceinline__ uint32_t pack_hi16(float a, float b) {
    uint32_t r;
    asm("prmt.b32 %0, %1, %2, 0x7632;" : "=r"(r) : "r"(__float_as_uint(a)), "r"(__float_as_uint(b)));
    return r;
}
__device__ __forceinline__ float trunc_bf16f(float v) {
    return __uint_as_float(__float_as_uint(v) & 0xFFFF0000u);
}

// ---------------------------------------------------------------------------
// RMSNorm -> bf16 hi/lo split
// ---------------------------------------------------------------------------
__global__ void rmsnorm_split_kernel(const float* __restrict__ x,
                                     const float* __restrict__ g,
                                     __nv_bfloat16* __restrict__ oh,
                                     __nv_bfloat16* __restrict__ ol) {
    int row = blockIdx.x;
    const float4* xr = reinterpret_cast<const float4*>(x + (size_t)row * D);
    float4 v = xr[threadIdx.x];
    float s = v.x * v.x + v.y * v.y + v.z * v.z + v.w * v.w;
    #pragma unroll
    for (int o = 16; o > 0; o >>= 1) s += __shfl_xor_sync(0xffffffffu, s, o);
    __shared__ float ws[8];
    if ((threadIdx.x & 31) == 0) ws[threadIdx.x >> 5] = s;
    __syncthreads();
    float tot = ws[0] + ws[1] + ws[2] + ws[3] + ws[4] + ws[5] + ws[6] + ws[7];
    float inv = rsqrtf(tot * (1.0f / (float)D) + EPS);
    float4 gv = reinterpret_cast<const float4*>(g)[threadIdx.x];
    float vals[4] = {v.x * inv * gv.x, v.y * inv * gv.y, v.z * inv * gv.z, v.w * inv * gv.w};
    __nv_bfloat16 h[4], l[4];
    #pragma unroll
    for (int j = 0; j < 4; j++) split2(vals[j], h[j], l[j]);
    size_t off = (size_t)row * D + threadIdx.x * 4;
    *reinterpret_cast<__nv_bfloat162*>(&oh[off])     = __halves2bfloat162(h[0], h[1]);
    *reinterpret_cast<__nv_bfloat162*>(&oh[off + 2]) = __halves2bfloat162(h[2], h[3]);
    *reinterpret_cast<__nv_bfloat162*>(&ol[off])     = __halves2bfloat162(l[0], l[1]);
    *reinterpret_cast<__nv_bfloat162*>(&ol[off + 2]) = __halves2bfloat162(l[2], l[3]);
}

// ---------------------------------------------------------------------------
// Weight transpose + bf16 split: W[K,N] -> Wt_hi/Wt_lo [N,K]
// ---------------------------------------------------------------------------
__global__ void transpose_split_kernel(const float* __restrict__ W, int K, int N,
                                       __nv_bfloat16* __restrict__ Th,
                                       __nv_bfloat16* __restrict__ Tl) {
    __shared__ float t[32][33];
    int k0 = blockIdx.y * 32, n0 = blockIdx.x * 32;
    int x = threadIdx.x, y = threadIdx.y;   // 32 x 8
    #pragma unroll
    for (int i = y; i < 32; i += 8)
        t[i][x] = W[(size_t)(k0 + i) * N + n0 + x];
    __syncthreads();
    #pragma unroll
    for (int b = y; b < 32; b += 8) {
        float v = t[x][b];
        __nv_bfloat16 h, l;
        split2(v, h, l);
        size_t o = (size_t)(n0 + b) * K + k0 + x;
        Th[o] = h;
        Tl[o] = l;
    }
}

// ---------------------------------------------------------------------------
// mma.sync split-bf16 GEMM, tile 128x256, warp 64x64, 2-stage cp.async.
// ---------------------------------------------------------------------------
#define EPI_BIAS 0
#define EPI_GELU 1
#define EPI_RES  2
#define EPI_QKV  3

// stage: Ah 16K | Al 16K | Bh 32K | Bl 32K = 96K
#define STAGE_BYTES 98304
#define TCG_SMEM (2 * STAGE_BYTES)

template <int EPI>
__global__ __launch_bounds__(256, 1)
void tcgemm_kernel(const __nv_bfloat16* __restrict__ Ah, const __nv_bfloat16* __restrict__ Al,
                   const __nv_bfloat16* __restrict__ Bh, const __nv_bfloat16* __restrict__ Bl,
                   const float* __restrict__ bias, const float* __restrict__ R,
                   float* __restrict__ C,
                   __nv_bfloat16* __restrict__ Oh, __nv_bfloat16* __restrict__ Ol,
                   __nv_bfloat16* __restrict__ Qh, __nv_bfloat16* __restrict__ Ql,
                   __nv_bfloat16* __restrict__ Kh, __nv_bfloat16* __restrict__ Kl,
                   __nv_bfloat16* __restrict__ Vh, __nv_bfloat16* __restrict__ Vl,
                   int M, int N, int K) {
    extern __shared__ __align__(1024) char smem[];
    uint32_t sbase = smem_to_u32(smem);
    const int tid = threadIdx.x;
    const int wid = tid >> 5, lid = tid & 31;
    const int wm = wid >> 2, wn = wid & 3;        // warp tile 64(m) x 64(n)
    const int bm = blockIdx.y * 128, bn = blockIdx.x * 256;

    auto load_chunk = [&](int c, int s) {
        uint32_t tb = sbase + s * STAGE_BYTES;
        // A tiles (hi, lo): 128 rows x 128B each
        #pragma unroll
        for (int t2 = 0; t2 < 2; t2++) {
            const __nv_bfloat16* src = t2 ? Al : Ah;
            uint32_t dst0 = tb + t2 * 16384;
            #pragma unroll
            for (int i = 0; i < 4; i++) {
                int u = tid + i * 256;
                int r = u >> 3, j = u & 7;
                uint32_t d = dst0 + SWZ(r * 128 + j * 16);
                const void* g = src + (size_t)(bm + r) * K + c * 64 + j * 8;
                asm volatile("cp.async.cg.shared.global [%0], [%1], 16;"
                             :: "r"(d), "l"(g) : "memory");
            }
        }
        // B tiles (hi, lo): 256 rows x 128B each
        #pragma unroll
        for (int t2 = 0; t2 < 2; t2++) {
            const __nv_bfloat16* src = t2 ? Bl : Bh;
            uint32_t dst0 = tb + 32768 + t2 * 32768;
            #pragma unroll
            for (int i = 0; i < 8; i++) {
                int u = tid + i * 256;
                int r = u >> 3, j = u & 7;
                uint32_t d = dst0 + SWZ(r * 128 + j * 16);
                const void* g = src + (size_t)(bn + r) * K + c * 64 + j * 8;
                asm volatile("cp.async.cg.shared.global [%0], [%1], 16;"
                             :: "r"(d), "l"(g) : "memory");
            }
        }
        asm volatile("cp.async.commit_group;" ::: "memory");
    };

    float acc[4][8][4];
    #pragma unroll
    for (int im = 0; im < 4; im++)
        #pragma unroll
        for (int in = 0; in < 8; in++)
            #pragma unroll
            for (int q = 0; q < 4; q++) acc[im][in][q] = 0.0f;

    const int nchunks = K >> 6;
    load_chunk(0, 0);

    const int arow = wm * 64 + (lid & 15);
    const int acol = (lid >> 4) * 16;
    const int brow = wn * 64 + (lid & 7);
    const int bcol = ((lid >> 3) & 1) * 16;

    for (int c = 0; c < nchunks; c++) {
        int s = c & 1;
        if (c + 1 < nchunks) {
            load_chunk(c + 1, s ^ 1);
            asm volatile("cp.async.wait_group 1;" ::: "memory");
        } else {
            asm volatile("cp.async.wait_group 0;" ::: "memory");
        }
        __syncthreads();

        uint32_t tb = sbase + s * STAGE_BYTES;
        uint32_t tAh = tb, tAl = tb + 16384, tBh = tb + 32768, tBl = tb + 65536;

        #pragma unroll
        for (int ks = 0; ks < 4; ks++) {
            uint32_t ah[4][4], al[4][4], bh[8][2], bl[8][2];
            #pragma unroll
            for (int im = 0; im < 4; im++) {
                uint32_t off = SWZ((arow + im * 16) * 128 + ks * 32 + acol);
                ldsm_x4(ah[im], tAh + off);
            }
            #pragma unroll
            for (int in = 0; in < 8; in++) {
                uint32_t off = SWZ((brow + in * 8) * 128 + ks * 32 + bcol);
                ldsm_x2(bh[in], tBh + off);
            }
            #pragma unroll
            for (int im = 0; im < 4; im++)
                #pragma unroll
                for (int in = 0; in < 8; in++)
                    mma_bf16_g(acc[im][in], ah[im], bh[in]);
            #pragma unroll
            for (int in = 0; in < 8; in++) {
                uint32_t off = SWZ((brow + in * 8) * 128 + ks * 32 + bcol);
                ldsm_x2(bl[in], tBl + off);
            }
            #pragma unroll
            for (int im = 0; im < 4; im++)
                #pragma unroll
                for (int in = 0; in < 8; in++)
                    mma_bf16_g(acc[im][in], ah[im], bl[in]);
            #pragma unroll
            for (int im = 0; im < 4; im++) {
                uint32_t off = SWZ((arow + im * 16) * 128 + ks * 32 + acol);
                ldsm_x4(al[im], tAl + off);
            }
            #pragma unroll
            for (int im = 0; im < 4; im++)
                #pragma unroll
                for (int in = 0; in < 8; in++)
                    mma_bf16_g(acc[im][in], al[im], bh[in]);
        }
        __syncthreads();
    }

    #pragma unroll
    for (int im = 0; im < 4; im++) {
        #pragma unroll
        for (int in = 0; in < 8; in++) {
            int m0 = bm + wm * 64 + im * 16 + (lid >> 2);
            int n0 = bn + wn * 64 + in * 8 + (lid & 3) * 2;
            float b0 = bias[n0], b1 = bias[n0 + 1];
            #pragma unroll
            for (int half = 0; half < 2; half++) {
                int m = m0 + half * 8;
                float v0 = acc[im][in][half * 2]     + b0;
                float v1 = acc[im][in][half * 2 + 1] + b1;
                if (EPI == EPI_QKV) {
                    int part = n0 >> 10;
                    int head = (n0 >> 6) & 15;
                    int d = n0 & 63;
                    int bb = m >> 11, t = m & 2047;
                    size_t dst = ((size_t)(bb * NH + head) * TSEQ + t) * HD + d;
                    __nv_bfloat16 h0, l0, h1, l1;
                    split2(v0, h0, l0);
                    split2(v1, h1, l1);
                    __nv_bfloat16* dh = (part == 0) ? Qh : (part == 1) ? Kh : Vh;
                    __nv_bfloat16* dl = (part == 0) ? Ql : (part == 1) ? Kl : Vl;
                    *reinterpret_cast<__nv_bfloat162*>(&dh[dst]) = __halves2bfloat162(h0, h1);
                    *reinterpret_cast<__nv_bfloat162*>(&dl[dst]) = __halves2bfloat162(l0, l1);
                } else if (EPI == EPI_GELU) {
                    size_t off = (size_t)m * N + n0;
                    float g0 = 0.5f * v0 * (1.0f + erff(v0 * 0.70710678118654752f));
                    float g1 = 0.5f * v1 * (1.0f + erff(v1 * 0.70710678118654752f));
                    __nv_bfloat16 h0, l0, h1, l1;
                    split2(g0, h0, l0);
                    split2(g1, h1, l1);
                    *reinterpret_cast<__nv_bfloat162*>(&Oh[off]) = __halves2bfloat162(h0, h1);
                    *reinterpret_cast<__nv_bfloat162*>(&Ol[off]) = __halves2bfloat162(l0, l1);
                } else {
                    size_t off = (size_t)m * N + n0;
                    if (EPI == EPI_RES) {
                        float2 rr = *reinterpret_cast<const float2*>(&R[off]);
                        v0 += rr.x; v1 += rr.y;
                    }
                    float2 o2 = make_float2(v0, v1);
                    *reinterpret_cast<float2*>(&C[off]) = o2;
                }
            }
        }
    }
}

// ---------------------------------------------------------------------------
// Tensor-core flash attention, pre-split inputs, double-buffered cp.async K/V.
// CTA = 128 q-rows x 1 head. Heavy-first scheduling (reversed qb).
// ---------------------------------------------------------------------------
#define ATTN_SMEM 98304

__global__ __launch_bounds__(256, 1)
void attn_mma_kernel(const __nv_bfloat16* __restrict__ Qh, const __nv_bfloat16* __restrict__ Ql,
                     const __nv_bfloat16* __restrict__ Kh, const __nv_bfloat16* __restrict__ Kl,
                     const __nv_bfloat16* __restrict__ Vh, const __nv_bfloat16* __restrict__ Vl,
                     __nv_bfloat16* __restrict__ oh, __nv_bfloat16* __restrict__ ol) {
    extern __shared__ __align__(1024) char smem_raw[];
    uint32_t sb = smem_to_u32(smem_raw);
    const uint32_t sQh = 0, sQl = 16384;

    const int tid = threadIdx.x;
    const int wid = tid >> 5, lid = tid & 31;
    const int qb = gridDim.x - 1 - blockIdx.x;   // heavy CTAs first
    const int h = blockIdx.y, b = blockIdx.z;
    const int qbase = qb * 128;
    const size_t hdbase = (size_t)(b * NH + h) * TSEQ * HD;

    const __nv_bfloat16* kvsrc[4] = {Kh + hdbase, Kl + hdbase, Vh + hdbase, Vl + hdbase};

    auto load_kv = [&](int c, int s) {
        uint32_t slot = sb + 32768 + s * 32768;
        int rowbase = c * 64;
        #pragma unroll
        for (int i = 0; i < 8; i++) {
            int u = tid + i * 256;
            int t4 = u >> 9;
            int c2 = u & 511;
            int r = c2 >> 3, j = c2 & 7;
            uint32_t d = slot + t4 * 8192 + SWZ(r * 128 + j * 16);
            const void* g = kvsrc[t4] + (size_t)(rowbase + r) * HD + j * 8;
            asm volatile("cp.async.cg.shared.global [%0], [%1], 16;"
                         :: "r"(d), "l"(g) : "memory");
        }
    };

    {
        const __nv_bfloat16* qhp = Qh + hdbase + (size_t)qbase * HD;
        const __nv_bfloat16* qlp = Ql + hdbase + (size_t)qbase * HD;
        #pragma unroll
        for (int i = 0; i < 4; i++) {
            int u = tid + i * 256;
            int r = u >> 3, j = u & 7;
            uint32_t o = SWZ(r * 128 + j * 16);
            asm volatile("cp.async.cg.shared.global [%0], [%1], 16;"
                         :: "r"(sb + sQh + o), "l"((const void*)(qhp + (size_t)r * HD + j * 8)) : "memory");
            asm volatile("cp.async.cg.shared.global [%0], [%1], 16;"
                         :: "r"(sb + sQl + o), "l"((const void*)(qlp + (size_t)r * HD + j * 8)) : "memory");
        }
        load_kv(0, 0);
        asm volatile("cp.async.commit_group;" ::: "memory");
    }

    float mrow[2] = {-1e30f, -1e30f};
    float lrow[2] = {0.0f, 0.0f};
    float oacc[8][4];
    #pragma unroll
    for (int t = 0; t < 8; t++)
        #pragma unroll
        for (int c = 0; c < 4; c++) oacc[t][c] = 0.0f;

    const int nchunks = 2 * qb + 2;
    const int wrow_hi = qbase + 16 * wid + 15;

    for (int kc = 0; kc < nchunks; kc++) {
        const int kbase = kc * 64;
        const int s = kc & 1;
        if (kc + 1 < nchunks) {
            load_kv(kc + 1, s ^ 1);
            asm volatile("cp.async.commit_group;" ::: "memory");
            asm volatile("cp.async.wait_group 1;" ::: "memory");
        } else {
            asm volatile("cp.async.wait_group 0;" ::: "memory");
        }
        __syncthreads();

        if (wrow_hi >= kbase) {
            const uint32_t slot = sb + 32768 + s * 32768;
            const uint32_t tKh = slot, tKl = slot + 8192, tVh = slot + 16384, tVl = slot + 24576;

            uint32_t qh[4][4], ql[4][4];
            {
                int qr = 16 * wid + (lid & 15);
                int qc = (lid >> 4) * 16;
                #pragma unroll
                for (int ks = 0; ks < 4; ks++) {
                    uint32_t off = SWZ(qr * 128 + ks * 32 + qc);
                    ldsm_x4(qh[ks], sb + sQh + off);
                    ldsm_x4(ql[ks], sb + sQl + off);
                }
            }
            float sacc[8][4];
            #pragma unroll
            for (int t = 0; t < 8; t++)
                #pragma unroll
                for (int c = 0; c < 4; c++) sacc[t][c] = 0.0f;

            {
                int kr = lid & 7;
                int kcb = ((lid >> 3) & 1) * 16;
                #pragma unroll
                for (int t = 0; t < 8; t++) {
                    #pragma unroll
                    for (int ks = 0; ks < 4; ks++) {
                        uint32_t off = SWZ((t * 8 + kr) * 128 + ks * 32 + kcb);
                        uint32_t bh2[2], bl2[2];
                        ldsm_x2(bh2, tKh + off);
                        ldsm_x2(bl2, tKl + off);
                        mma_bf16_g(sacc[t], qh[ks], bh2);
                        mma_bf16_g(sacc[t], ql[ks], bh2);
                        mma_bf16_g(sacc[t], qh[ks], bl2);
                    }
                }
            }

            if (kc >= 2 * qb) {
                int row0 = qbase + 16 * wid + (lid >> 2);
                #pragma unroll
                for (int t = 0; t < 8; t++) {
                    int col = kbase + t * 8 + 2 * (lid & 3);
                    if (col > row0)     sacc[t][0] = -1e30f;
                    if (col + 1 > row0) sacc[t][1] = -1e30f;
                    if (col > row0 + 8)     sacc[t][2] = -1e30f;
                    if (col + 1 > row0 + 8) sacc[t][3] = -1e30f;
                }
            }

            #pragma unroll
            for (int rr = 0; rr < 2; rr++) {
                float mx = -1e30f;
                #pragma unroll
                for (int t = 0; t < 8; t++)
                    mx = fmaxf(mx, fmaxf(sacc[t][2 * rr], sacc[t][2 * rr + 1]));
                mx = fmaxf(mx, __shfl_xor_sync(0xffffffffu, mx, 1));
                mx = fmaxf(mx, __shfl_xor_sync(0xffffffffu, mx, 2));
                float mn = fmaxf(mrow[rr], mx);
                float sc = __expf(mrow[rr] - mn);
                mrow[rr] = mn;
                float rs = 0.0f;
                #pragma unroll
                for (int t = 0; t < 8; t++) {
                    float p0 = __expf(sacc[t][2 * rr] - mn);
                    float p1 = __expf(sacc[t][2 * rr + 1] - mn);
                    sacc[t][2 * rr] = p0; sacc[t][2 * rr + 1] = p1;
                    rs += p0 + p1;
                }
                lrow[rr] = lrow[rr] * sc + rs;
                #pragma unroll
                for (int t = 0; t < 8; t++) {
                    oacc[t][2 * rr]     *= sc;
                    oacc[t][2 * rr + 1] *= sc;
                }
            }

            {
                int vr = (lid & 7) + ((lid >> 3) & 1) * 8;
                #pragma unroll
                for (int j = 0; j < 4; j++) {
                    uint32_t ph[4], pl[4];
                    #pragma unroll
                    for (int half = 0; half < 2; half++) {
                        float a0 = sacc[2 * j + half][0], a1 = sacc[2 * j + half][1];
                        float a2 = sacc[2 * j + half][2], a3 = sacc[2 * j + half][3];
                        ph[0 + 2 * half] = pack_hi16(a0, a1);
                        ph[1 + 2 * half] = pack_hi16(a2, a3);
                        pl[0 + 2 * half] = pack_bf16x2(a0 - trunc_bf16f(a0), a1 - trunc_bf16f(a1));
                        pl[1 + 2 * half] = pack_bf16x2(a2 - trunc_bf16f(a2), a3 - trunc_bf16f(a3));
                    }
                    #pragma unroll
                    for (int t = 0; t < 8; t++) {
                        uint32_t voff = SWZ((j * 16 + vr) * 128 + t * 16);
                        uint32_t vh2[2], vl2[2];
                        ldsm_x2_trans(vh2, tVh + voff);
                        ldsm_x2_trans(vl2, tVl + voff);
                        mma_bf16_g(oacc[t], ph, vh2);
                        mma_bf16_g(oacc[t], pl, vh2);
                        mma_bf16_g(oacc[t], ph, vl2);
                    }
                }
            }
        }
        __syncthreads();
    }

    lrow[0] += __shfl_xor_sync(0xffffffffu, lrow[0], 1);
    lrow[0] += __shfl_xor_sync(0xffffffffu, lrow[0], 2);
    lrow[1] += __shfl_xor_sync(0xffffffffu, lrow[1], 1);
    lrow[1] += __shfl_xor_sync(0xffffffffu, lrow[1], 2);
    float inv0 = 0.03125f / lrow[0];
    float inv1 = 0.03125f / lrow[1];

    const size_t tok0 = (size_t)b * TSEQ;
    #pragma unroll
    for (int rr = 0; rr < 2; rr++) {
        float inv = rr ? inv1 : inv0;
        int row = qbase + 16 * wid + (lid >> 2) + rr * 8;
        size_t base = (tok0 + row) * (size_t)D + h * HD + 2 * (lid & 3);
        #pragma unroll
        for (int t = 0; t < 8; t++) {
            float v0 = oacc[t][2 * rr] * inv;
            float v1 = oacc[t][2 * rr + 1] * inv;
            __nv_bfloat16 h0, l0, h1, l1;
            split2(v0, h0, l0);
            split2(v1, h1, l1);
            *reinterpret_cast<__nv_bfloat162*>(&oh[base + t * 8]) = __halves2bfloat162(h0, h1);
            *reinterpret_cast<__nv_bfloat162*>(&ol[base + t * 8]) = __halves2bfloat162(l0, l1);
        }
    }
}

// ---------------------------------------------------------------------------
// Launch
// ---------------------------------------------------------------------------
extern "C" void kernel_launch(void* const* d_in, const int* in_sizes, int n_in,
                              void* d_out, int out_size) {
    const float* x      = (const float*)d_in[0];
    const float* w_attn = (const float*)d_in[1];
    const float* b_attn = (const float*)d_in[2];
    const float* w_proj = (const float*)d_in[3];
    const float* b_proj = (const float*)d_in[4];
    const float* w_fc1  = (const float*)d_in[5];
    const float* b_fc1  = (const float*)d_in[6];
    const float* w_fc2  = (const float*)d_in[7];
    const float* b_fc2  = (const float*)d_in[8];
    const float* g1     = (const float*)d_in[9];
    const float* g2     = (const float*)d_in[10];
    float* out = (float*)d_out;

    __nv_bfloat16 *ah, *al, *bh, *bl, *wth, *wtl;
    __nv_bfloat16 *qh, *ql, *kh, *kl, *vh, *vl;
    cudaGetSymbolAddress((void**)&ah,  g_ah);
    cudaGetSymbolAddress((void**)&al,  g_al);
    cudaGetSymbolAddress((void**)&bh,  g_bh);
    cudaGetSymbolAddress((void**)&bl,  g_bl);
    cudaGetSymbolAddress((void**)&wth, g_wth);
    cudaGetSymbolAddress((void**)&wtl, g_wtl);
    cudaGetSymbolAddress((void**)&qh,  g_qh);
    cudaGetSymbolAddress((void**)&ql,  g_ql);
    cudaGetSymbolAddress((void**)&kh,  g_kh);
    cudaGetSymbolAddress((void**)&kl,  g_kl);
    cudaGetSymbolAddress((void**)&vh,  g_vh);
    cudaGetSymbolAddress((void**)&vl,  g_vl);

    cudaFuncSetAttribute(attn_mma_kernel, cudaFuncAttributeMaxDynamicSharedMemorySize, ATTN_SMEM);
    cudaFuncSetAttribute(tcgemm_kernel<EPI_BIAS>, cudaFuncAttributeMaxDynamicSharedMemorySize, TCG_SMEM);
    cudaFuncSetAttribute(tcgemm_kernel<EPI_GELU>, cudaFuncAttributeMaxDynamicSharedMemorySize, TCG_SMEM);
    cudaFuncSetAttribute(tcgemm_kernel<EPI_RES>,  cudaFuncAttributeMaxDynamicSharedMemorySize, TCG_SMEM);
    cudaFuncSetAttribute(tcgemm_kernel<EPI_QKV>,  cudaFuncAttributeMaxDynamicSharedMemorySize, TCG_SMEM);

    dim3 tp(32, 8);

    // 1. rmsnorm(x, g1) -> ah/al
    rmsnorm_split_kernel<<<NTOK, 256>>>(x, g1, ah, al);
    // 2. qkv gemm -> pre-split q/k/v per head
    transpose_split_kernel<<<dim3(D3 / 32, D / 32), tp>>>(w_attn, D, D3, wth, wtl);
    tcgemm_kernel<EPI_QKV><<<dim3(D3 / 256, NTOK / 128), 256, TCG_SMEM>>>(
        ah, al, wth, wtl, b_attn, nullptr, nullptr, nullptr, nullptr,
        qh, ql, kh, kl, vh, vl, NTOK, D3, D);
    // 3. attention -> ah/al
    attn_mma_kernel<<<dim3(TSEQ / 128, NH, NBATCH), 256, ATTN_SMEM>>>(
        qh, ql, kh, kl, vh, vl, ah, al);
    // 4. out = x + o @ w_proj + b_proj
    transpose_split_kernel<<<dim3(D / 32, D / 32), tp>>>(w_proj, D, D, wth, wtl);
    tcgemm_kernel<EPI_RES><<<dim3(D / 256, NTOK / 128), 256, TCG_SMEM>>>(
        ah, al, wth, wtl, b_proj, x, out, nullptr, nullptr,
        nullptr, nullptr, nullptr, nullptr, nullptr, nullptr, NTOK, D, D);
    // 5. rmsnorm(out, g2) -> ah/al
    rmsnorm_split_kernel<<<NTOK, 256>>>(out, g2, ah, al);
    // 6. bh/bl = gelu(h @ w_fc1 + b_fc1) split
    transpose_split_kernel<<<dim3(D4 / 32, D / 32), tp>>>(w_fc1, D, D4, wth, wtl);
    tcgemm_kernel<EPI_GELU><<<dim3(D4 / 256, NTOK / 128), 256, TCG_SMEM>>>(
        ah, al, wth, wtl, b_fc1, nullptr, nullptr, bh, bl,
        nullptr, nullptr, nullptr, nullptr, nullptr, nullptr, NTOK, D4, D);
    // 7. out = out + act @ w_fc2 + b_fc2
    transpose_split_kernel<<<dim3(D / 32, D4 / 32), tp>>>(w_fc2, D4, D, wth, wtl);
    tcgemm_kernel<EPI_RES><<<dim3(D / 256, NTOK / 128), 256, TCG_SMEM>>>(
        bh, bl, wth, wtl, b_fc2, out, out, nullptr, nullptr,
        nullptr, nullptr, nullptr, nullptr, nullptr, nullptr, NTOK, D, D4);
}